// round 17
// baseline (speedup 1.0000x reference)
#include <cuda_runtime.h>
#include <cuda_bf16.h>
#include <math.h>
#include <stdint.h>

// ---------------- problem constants ----------------
#define BATCH 512
#define NPRIM 32
#define NCLASS 10

// ---------------- scratch (static device memory; no allocs allowed) ----------------
__device__ __align__(256) unsigned short g_h1h[BATCH * 400 * 256];   // 100 MB
__device__ __align__(256) unsigned short g_h1l[BATCH * 400 * 256];   // 100 MB
__device__ __align__(256) unsigned short g_Wph[25 * 4 * 256 * 64];   // 3.3 MB
__device__ __align__(256) unsigned short g_c1Wh[256 * 96];
__device__ __align__(256) unsigned short g_cWb[4 * 256 * 64];
// primary caps activations bf16 hi/lo, layout [b][pix64][i32][c8]
__device__ __align__(256) unsigned short g_pbh[BATCH * 64 * 32 * 8]; // 16.8 MB
__device__ __align__(256) unsigned short g_pbl[BATCH * 64 * 32 * 8]; // 16.8 MB
// FC weights prepacked: [ktile][n_pad][k64] bf16
__device__ __align__(256) unsigned short g_fw1[3 * 512 * 64];
__device__ __align__(256) unsigned short g_fw2[8 * 1024 * 64];
__device__ __align__(256) unsigned short g_fw3[16 * 1024 * 64];
__device__ float g_c[BATCH * 32 * 8 * 4];                // [b][o][a][pos]
__device__ float g_masked[BATCH * 160];
__device__ float g_r1[BATCH * 512];
__device__ float g_r2[BATCH * 1024];

// ---------------- cp.async helpers ----------------
__device__ __forceinline__ void cp16(void* smem, const void* g) {
    unsigned s;
    asm("{ .reg .u64 t; cvta.to.shared.u64 t, %1; cvt.u32.u64 %0, t; }"
        : "=r"(s) : "l"(smem));
    asm volatile("cp.async.cg.shared.global [%0], [%1], 16;" :: "r"(s), "l"(g));
}
__device__ __forceinline__ void cp16z(void* smem, const void* g, int valid) {
    unsigned s;
    asm("{ .reg .u64 t; cvta.to.shared.u64 t, %1; cvt.u32.u64 %0, t; }"
        : "=r"(s) : "l"(smem));
    asm volatile("cp.async.cg.shared.global [%0], [%1], 16, %2;"
        :: "r"(s), "l"(g), "r"(valid ? 16 : 0));
}
__device__ __forceinline__ void cp_commit() { asm volatile("cp.async.commit_group;"); }
__device__ __forceinline__ void cp_wait0() {
    asm volatile("cp.async.wait_group 0;" ::: "memory");
}

// ---------------- mma.sync bf16 + ldmatrix (sm_80+ legacy tensor path) ----------------
__device__ __forceinline__ void mma_bf16(float* d, const uint32_t* a, uint32_t b0,
                                         uint32_t b1) {
    asm volatile(
        "mma.sync.aligned.m16n8k16.row.col.f32.bf16.bf16.f32 "
        "{%0,%1,%2,%3}, {%4,%5,%6,%7}, {%8,%9}, {%0,%1,%2,%3};"
        : "+f"(d[0]), "+f"(d[1]), "+f"(d[2]), "+f"(d[3])
        : "r"(a[0]), "r"(a[1]), "r"(a[2]), "r"(a[3]), "r"(b0), "r"(b1));
}
__device__ __forceinline__ void ldm_x4(uint32_t* r, uint32_t addr) {
    asm volatile("ldmatrix.sync.aligned.m8n8.x4.shared.b16 {%0,%1,%2,%3}, [%4];"
        : "=r"(r[0]), "=r"(r[1]), "=r"(r[2]), "=r"(r[3]) : "r"(addr));
}
__device__ __forceinline__ uint32_t smem_u32(const void* p) {
    uint32_t a;
    asm("{ .reg .u64 t; cvta.to.shared.u64 t, %1; cvt.u32.u64 %0, t; }" : "=r"(a) : "l"(p));
    return a;
}
__device__ __forceinline__ uint32_t pack_bf16x2(float v0, float v1) {
    __nv_bfloat16 h0 = __float2bfloat16(v0);
    __nv_bfloat16 h1 = __float2bfloat16(v1);
    return (uint32_t)__bfloat16_as_ushort(h0) | ((uint32_t)__bfloat16_as_ushort(h1) << 16);
}

// ---------------- prepacks ----------------
__global__ void prepack_W(const float* __restrict__ w) {
    int idx = blockIdx.x * 256 + threadIdx.x;
    if (idx >= 25 * 4 * 256 * 64) return;
    int ic = idx & 63;
    int oc = (idx >> 6) & 255;
    int chunk = (idx >> 14) & 3;
    int kpos = idx >> 16;
    float v = w[oc * 6400 + (chunk * 64 + ic) * 25 + kpos];
    g_Wph[idx] = __bfloat16_as_ushort(__float2bfloat16(v));
}
__global__ void prepack_c1(const float* __restrict__ w) {
    int idx = blockIdx.x * 256 + threadIdx.x;
    if (idx >= 256 * 96) return;
    int k = idx % 96, oc = idx / 96;
    float v = (k < 81) ? w[oc * 81 + k] : 0.f;
    g_c1Wh[idx] = __bfloat16_as_ushort(__float2bfloat16(v));
}
__global__ void prepack_cc(const float* __restrict__ w) {
    int idx = blockIdx.x * 256 + threadIdx.x;
    if (idx >= 4 * 256 * 64) return;
    int j = idx & 63;
    int oc = (idx >> 6) & 255;
    int q = idx >> 14;
    int kk = q * 64 + j;
    int kpos = kk >> 3, c = kk & 7;
    float v = (kpos < 25) ? w[oc * 200 + c * 25 + kpos] : 0.f;
    g_cWb[idx] = __bfloat16_as_ushort(__float2bfloat16(v));
}
__global__ void prepack_fc(const float* __restrict__ w, unsigned short* __restrict__ dst,
                           int K_real, int N_real, int N_pad, int total) {
    int idx = blockIdx.x * 256 + threadIdx.x;
    if (idx >= total) return;
    int j = idx & 63;
    int n = (idx >> 6) % N_pad;
    int q = idx / (N_pad * 64);
    int k = q * 64 + j;
    float v = (k < K_real && n < N_real) ? w[k * N_real + n] : 0.f;
    dst[idx] = __bfloat16_as_ushort(__float2bfloat16(v));
}

// ---------------- conv1 via mma.sync: M=512*400 rows, N=256 ch, K=96 (81 taps) --------
#define C1P 208
#define C1_IMG 0
#define C1_AH 6400
#define C1_AL (C1_AH + 128 * C1P)
#define C1_BH (C1_AL + 128 * C1P)
#define C1_SMEM (C1_BH + 256 * C1P)    // 112896

__global__ __launch_bounds__(512, 1) void conv1_mma_kernel(
    const float* __restrict__ x, const float* __restrict__ bias) {
    extern __shared__ char c1s[];
    int tid = threadIdx.x;
    int blk = blockIdx.x;
    int r0 = blk * 128;
    int b0 = r0 / 400;

    for (int i = 0; i < 6; i++) {
        int q = tid + i * 512;
        int row = q / 12, seg = q % 12;
        cp16(c1s + C1_BH + row * C1P + seg * 16, &g_c1Wh[row * 96 + seg * 8]);
    }
    cp_commit();

    float* img = (float*)(c1s + C1_IMG);
    int b1 = (r0 + 127) / 400;
    for (int i = tid; i < 784; i += 512) {
        img[i] = x[(size_t)b0 * 784 + i];
        img[784 + i] = (b1 != b0) ? x[(size_t)b1 * 784 + i] : 0.f;
    }
    __syncthreads();

    uint32_t* ah = (uint32_t*)(c1s + C1_AH);
    uint32_t* al = (uint32_t*)(c1s + C1_AL);
#pragma unroll
    for (int i = 0; i < 12; i++) {
        int w = tid + i * 512;
        int r = w / 48, cw = w % 48;
        int R = r0 + r;
        int b = R / 400, pos = R - b * 400;
        int y = pos / 20, xx = pos - y * 20;
        const float* ip = img + (b - b0) * 784;
        float v[2];
#pragma unroll
        for (int h = 0; h < 2; h++) {
            int c = cw * 2 + h;
            float val = 0.f;
            if (c < 81) {
                int kh = c / 9, kw = c - kh * 9;
                val = ip[(y + kh) * 28 + xx + kw];
            }
            v[h] = val;
        }
        __nv_bfloat16 h0 = __float2bfloat16(v[0]);
        __nv_bfloat16 h1 = __float2bfloat16(v[1]);
        float l0 = v[0] - __bfloat162float(h0);
        float l1 = v[1] - __bfloat162float(h1);
        int off = (r * C1P >> 2) + cw;
        ah[off] = (uint32_t)__bfloat16_as_ushort(h0) |
                  ((uint32_t)__bfloat16_as_ushort(h1) << 16);
        al[off] = pack_bf16x2(l0, l1);
    }
    cp_wait0();
    __syncthreads();

    int wid = tid >> 5, lane = tid & 31;
    int g = lane >> 2, c = lane & 3;
    int warpM = wid & 1;
    int warpN = wid >> 1;
    uint32_t sbase = smem_u32(c1s);
    uint32_t aBase = sbase + C1_AH +
                     (uint32_t)(warpM * 64 + (lane & 15)) * C1P + ((lane >> 4) << 4);
    uint32_t bBase = sbase + C1_BH +
                     (uint32_t)(warpN * 32 + (lane & 7) + ((lane & 16) >> 1)) * C1P +
                     ((lane & 8) ? 16u : 0u);

    float acc[4][4][4];
#pragma unroll
    for (int mt = 0; mt < 4; mt++)
#pragma unroll
        for (int j = 0; j < 4; j++)
#pragma unroll
            for (int q = 0; q < 4; q++) acc[mt][j][q] = 0.f;

#pragma unroll
    for (int kk = 0; kk < 6; kk++) {
        uint32_t bh[2][4];
#pragma unroll
        for (int np = 0; np < 2; np++)
            ldm_x4(bh[np], bBase + np * (16 * C1P) + kk * 32);
#pragma unroll
        for (int mt = 0; mt < 4; mt++) {
            uint32_t ahf[4], alf[4];
            ldm_x4(ahf, aBase + mt * (16 * C1P) + kk * 32);
            ldm_x4(alf, aBase + (C1_AL - C1_AH) + mt * (16 * C1P) + kk * 32);
#pragma unroll
            for (int np = 0; np < 2; np++)
#pragma unroll
                for (int nt = 0; nt < 2; nt++)
                    mma_bf16(acc[mt][np * 2 + nt], ahf, bh[np][nt * 2], bh[np][nt * 2 + 1]);
#pragma unroll
            for (int np = 0; np < 2; np++)
#pragma unroll
                for (int nt = 0; nt < 2; nt++)
                    mma_bf16(acc[mt][np * 2 + nt], alf, bh[np][nt * 2], bh[np][nt * 2 + 1]);
        }
    }

#pragma unroll
    for (int mt = 0; mt < 4; mt++) {
        int R1 = r0 + warpM * 64 + mt * 16 + g;
        int R2 = R1 + 8;
#pragma unroll
        for (int j = 0; j < 4; j++) {
            int ch = warpN * 32 + j * 8 + 2 * c;
            float bv0 = __ldg(&bias[ch]);
            float bv1 = __ldg(&bias[ch + 1]);
            float v0 = acc[mt][j][0] + bv0; v0 = v0 > 0.f ? v0 : 0.f;
            float v1 = acc[mt][j][1] + bv1; v1 = v1 > 0.f ? v1 : 0.f;
            float v2 = acc[mt][j][2] + bv0; v2 = v2 > 0.f ? v2 : 0.f;
            float v3 = acc[mt][j][3] + bv1; v3 = v3 > 0.f ? v3 : 0.f;
            __nv_bfloat16 h0 = __float2bfloat16(v0);
            __nv_bfloat16 h1 = __float2bfloat16(v1);
            __nv_bfloat16 h2 = __float2bfloat16(v2);
            __nv_bfloat16 h3 = __float2bfloat16(v3);
            uint32_t hw1 = (uint32_t)__bfloat16_as_ushort(h0) |
                           ((uint32_t)__bfloat16_as_ushort(h1) << 16);
            uint32_t hw2 = (uint32_t)__bfloat16_as_ushort(h2) |
                           ((uint32_t)__bfloat16_as_ushort(h3) << 16);
            uint32_t lw1 = pack_bf16x2(v0 - __bfloat162float(h0), v1 - __bfloat162float(h1));
            uint32_t lw2 = pack_bf16x2(v2 - __bfloat162float(h2), v3 - __bfloat162float(h3));
            size_t o1 = ((size_t)R1 * 256 + ch) >> 1;
            size_t o2 = ((size_t)R2 * 256 + ch) >> 1;
            ((uint32_t*)g_h1h)[o1] = hw1;
            ((uint32_t*)g_h1l)[o1] = lw1;
            ((uint32_t*)g_h1h)[o2] = hw2;
            ((uint32_t*)g_h1l)[o2] = lw2;
        }
    }
}

// ---------------- primary caps conv via mma.sync + ldmatrix (2-product, 1 sync/step) --
#define PITCH 144
#define OFF_AH 0
#define OFF_AL 18432
#define OFF_BH 36864
#define PBUF 73728
#define PRIM_SMEM (2 * PBUF)           // 147456

extern __shared__ char psmem[];

__device__ __forceinline__ void prim_load_step(int buf, int s, int tid, int b0) {
    int kpos = s >> 2, chunk = s & 3;
    int kh = kpos / 5, kw = kpos - kh * 5;
    char* base = psmem + buf * PBUF;
#pragma unroll
    for (int ii = 0; ii < 2; ii++) {
        int i = tid + ii * 512;
        int r = i >> 3, seg = i & 7;
        int batch = r >> 6, pos = r & 63;
        int y = pos >> 3, xx = pos & 7;
        int pix = (2 * y + kh) * 20 + 2 * xx + kw;
        size_t src = ((size_t)(b0 + batch) * 400 + pix) * 256 + chunk * 64 + seg * 8;
        char* d = base + r * PITCH + seg * 16;
        cp16(d + OFF_AH, &g_h1h[src]);
        cp16(d + OFF_AL, &g_h1l[src]);
    }
    size_t wbase = (size_t)s * 16384;
#pragma unroll
    for (int ii = 0; ii < 4; ii++) {
        int i = tid + ii * 512;
        int r = i >> 3, seg = i & 7;
        cp16(base + OFF_BH + r * PITCH + seg * 16, &g_Wph[wbase + r * 64 + seg * 8]);
    }
}

__global__ __launch_bounds__(512, 1) void prim_mma_kernel(const float* __restrict__ prim_bias) {
    int tid = threadIdx.x;
    int b0 = blockIdx.x * 2;
    int wid = tid >> 5, lane = tid & 31;
    int g = lane >> 2, c = lane & 3;
    int warpM = wid & 1;
    int warpN = wid >> 1;

    uint32_t sbase = smem_u32(psmem);
    uint32_t aOff = (uint32_t)(warpM * 64 + (lane & 15)) * PITCH + ((lane >> 4) << 4);
    uint32_t bRow = (uint32_t)(warpN * 32 + (lane & 7) + ((lane & 16) >> 1));
    uint32_t bOff = bRow * PITCH + ((lane & 8) ? 16u : 0u);

    float acc[4][4][4];
#pragma unroll
    for (int mt = 0; mt < 4; mt++)
#pragma unroll
        for (int j = 0; j < 4; j++)
#pragma unroll
            for (int q = 0; q < 4; q++) acc[mt][j][q] = 0.f;

    prim_load_step(0, 0, tid, b0);
    cp_commit();

    for (int s = 0; s < 100; s++) {
        int buf = s & 1;
        cp_wait0();
        __syncthreads();
        if (s + 1 < 100) {
            prim_load_step(buf ^ 1, s + 1, tid, b0);
            cp_commit();
        }
        uint32_t tbase = sbase + buf * PBUF;
        uint32_t aBase = tbase + OFF_AH + aOff;
        uint32_t bBase = tbase + OFF_BH + bOff;
#pragma unroll
        for (int kk = 0; kk < 4; kk++) {
            uint32_t bh[2][4];
#pragma unroll
            for (int np = 0; np < 2; np++)
                ldm_x4(bh[np], bBase + np * (16 * PITCH) + kk * 32);
#pragma unroll
            for (int mt = 0; mt < 4; mt++) {
                uint32_t ah[4], al[4];
                ldm_x4(ah, aBase + mt * (16 * PITCH) + kk * 32);
                ldm_x4(al, aBase + (OFF_AL - OFF_AH) + mt * (16 * PITCH) + kk * 32);
#pragma unroll
                for (int np = 0; np < 2; np++)
#pragma unroll
                    for (int nt = 0; nt < 2; nt++)
                        mma_bf16(acc[mt][np * 2 + nt], ah, bh[np][nt * 2], bh[np][nt * 2 + 1]);
#pragma unroll
                for (int np = 0; np < 2; np++)
#pragma unroll
                    for (int nt = 0; nt < 2; nt++)
                        mma_bf16(acc[mt][np * 2 + nt], al, bh[np][nt * 2], bh[np][nt * 2 + 1]);
            }
        }
    }

    int b_ = b0 + warpM;
#pragma unroll
    for (int mt = 0; mt < 4; mt++) {
        int pos1 = mt * 16 + g;
        int pos2 = pos1 + 8;
#pragma unroll
        for (int j = 0; j < 4; j++) {
            int caps = warpN * 4 + j;
            float bv0 = __ldg(&prim_bias[caps * 8 + 2 * c]);
            float bv1 = __ldg(&prim_bias[caps * 8 + 2 * c + 1]);
            float v0 = acc[mt][j][0] * (1.f / 32.f) + bv0;
            float v1 = acc[mt][j][1] * (1.f / 32.f) + bv1;
            float v2 = acc[mt][j][2] * (1.f / 32.f) + bv0;
            float v3 = acc[mt][j][3] * (1.f / 32.f) + bv1;
            float na = v0 * v0 + v1 * v1;
            float nb = v2 * v2 + v3 * v3;
            na += __shfl_xor_sync(0xFFFFFFFFu, na, 1);
            na += __shfl_xor_sync(0xFFFFFFFFu, na, 2);
            nb += __shfl_xor_sync(0xFFFFFFFFu, nb, 1);
            nb += __shfl_xor_sync(0xFFFFFFFFu, nb, 2);
            float fa = (na / (1.f + na)) * rsqrtf(na + 1e-8f);
            float fb = (nb / (1.f + nb)) * rsqrtf(nb + 1e-8f);
            float s0 = v0 * fa, s1 = v1 * fa, s2 = v2 * fb, s3 = v3 * fb;
            __nv_bfloat16 h0 = __float2bfloat16(s0);
            __nv_bfloat16 h1 = __float2bfloat16(s1);
            __nv_bfloat16 h2 = __float2bfloat16(s2);
            __nv_bfloat16 h3 = __float2bfloat16(s3);
            size_t i1 = (((size_t)b_ * 64 + pos1) * 32 + caps) * 8 + 2 * c;
            size_t i2 = (((size_t)b_ * 64 + pos2) * 32 + caps) * 8 + 2 * c;
            ((uint32_t*)g_pbh)[i1 >> 1] =
                (uint32_t)__bfloat16_as_ushort(h0) | ((uint32_t)__bfloat16_as_ushort(h1) << 16);
            ((uint32_t*)g_pbl)[i1 >> 1] =
                pack_bf16x2(s0 - __bfloat162float(h0), s1 - __bfloat162float(h1));
            ((uint32_t*)g_pbh)[i2 >> 1] =
                (uint32_t)__bfloat16_as_ushort(h2) | ((uint32_t)__bfloat16_as_ushort(h3) << 16);
            ((uint32_t*)g_pbl)[i2 >> 1] =
                pack_bf16x2(s2 - __bfloat162float(h2), s3 - __bfloat162float(h3));
        }
    }
}

// ---------------- FUSED conv-caps votes (mma.sync) + routing --------------------------
// M=128 (4pos x 32i), N=256 oc, K=4x64. Votes land in smem; routing runs in-block.
// smem: MMA phase uses 2x73728; routing phase overlays:
//   svf [32768 fl] | slog [4096 fl] | sroute [4096 fl] | sact [1024 fl] = 167936 B
#define V_AH 0
#define V_AL 18432
#define V_BH 36864
#define VBUF 73728
#define V_SMEM 167936

__device__ __forceinline__ void cc_load_step(char* vs, int buf, int q, int tid, int b) {
    char* base = vs + buf * VBUF;
#pragma unroll
    for (int ii = 0; ii < 2; ii++) {
        int idx = tid + ii * 512;
        int r = idx >> 3, seg = idx & 7;
        int pos = r >> 5, i = r & 31;
        int kpos = q * 8 + seg;
        int kh = kpos / 5, kw = kpos - kh * 5;
        int oy = pos >> 1, ox = pos & 1;
        int pix = (2 * oy + kh) * 8 + 2 * ox + kw;
        size_t src = (((size_t)b * 64 + pix) * 32 + i) * 8;
        int valid = (kpos < 25);
        char* d = base + r * PITCH + seg * 16;
        cp16z(d + V_AH, &g_pbh[src], valid);
        cp16z(d + V_AL, &g_pbl[src], valid);
    }
    size_t wbase = (size_t)q * 16384;
#pragma unroll
    for (int ii = 0; ii < 4; ii++) {
        int idx = tid + ii * 512;
        int r = idx >> 3, seg = idx & 7;
        cp16(base + V_BH + r * PITCH + seg * 16, &g_cWb[wbase + r * 64 + seg * 8]);
    }
}

__global__ __launch_bounds__(512, 1) void cc_votes_rout_kernel(
    const float* __restrict__ conv_bias) {
    extern __shared__ char vsm[];
    int tid = threadIdx.x;
    int b = blockIdx.x;
    int wid = tid >> 5, lane = tid & 31;
    int g = lane >> 2, c = lane & 3;
    int warpM = wid & 1;
    int warpN = wid >> 1;

    uint32_t sbase = smem_u32(vsm);
    uint32_t aOff = (uint32_t)(warpM * 64 + (lane & 15)) * PITCH + ((lane >> 4) << 4);
    uint32_t bRow = (uint32_t)(warpN * 32 + (lane & 7) + ((lane & 16) >> 1));
    uint32_t bOff = bRow * PITCH + ((lane & 8) ? 16u : 0u);

    float acc[4][4][4];
#pragma unroll
    for (int mt = 0; mt < 4; mt++)
#pragma unroll
        for (int j = 0; j < 4; j++)
#pragma unroll
            for (int q = 0; q < 4; q++) acc[mt][j][q] = 0.f;

    cc_load_step(vsm, 0, 0, tid, b);
    cp_commit();

    for (int s = 0; s < 4; s++) {
        int buf = s & 1;
        cp_wait0();
        __syncthreads();
        if (s + 1 < 4) {
            cc_load_step(vsm, buf ^ 1, s + 1, tid, b);
            cp_commit();
        }
        uint32_t tbase = sbase + buf * VBUF;
        uint32_t aBase = tbase + V_AH + aOff;
        uint32_t bBase = tbase + V_BH + bOff;
#pragma unroll
        for (int kk = 0; kk < 4; kk++) {
            uint32_t bh[2][4];
#pragma unroll
            for (int np = 0; np < 2; np++)
                ldm_x4(bh[np], bBase + np * (16 * PITCH) + kk * 32);
#pragma unroll
            for (int mt = 0; mt < 4; mt++) {
                uint32_t ah[4], al[4];
                ldm_x4(ah, aBase + mt * (16 * PITCH) + kk * 32);
                ldm_x4(al, aBase + (V_AL - V_AH) + mt * (16 * PITCH) + kk * 32);
#pragma unroll
                for (int np = 0; np < 2; np++)
#pragma unroll
                    for (int nt = 0; nt < 2; nt++)
                        mma_bf16(acc[mt][np * 2 + nt], ah, bh[np][nt * 2], bh[np][nt * 2 + 1]);
#pragma unroll
                for (int np = 0; np < 2; np++)
#pragma unroll
                    for (int nt = 0; nt < 2; nt++)
                        mma_bf16(acc[mt][np * 2 + nt], al, bh[np][nt * 2], bh[np][nt * 2 + 1]);
            }
        }
    }
    __syncthreads();     // all warps done reading pipeline buffers

    // overlay routing arrays; write votes to smem [row128][oc256]
    float* svf = (float*)vsm;            // 32768 fl
    float* slog = svf + 32768;           // 4096 fl  (pos*1024 + i*32 + o)
    float* srt = slog + 4096;            // 4096 fl
    float* sact = srt + 4096;            // 1024 fl  (pos*256 + oc)
#pragma unroll
    for (int mt = 0; mt < 4; mt++) {
        int r1 = warpM * 64 + mt * 16 + g;
        int r2 = r1 + 8;
#pragma unroll
        for (int j = 0; j < 4; j++) {
            int col = warpN * 32 + j * 8 + 2 * c;
            *(float2*)&svf[r1 * 256 + col] = make_float2(acc[mt][j][0], acc[mt][j][1]);
            *(float2*)&svf[r2 * 256 + col] = make_float2(acc[mt][j][2], acc[mt][j][3]);
        }
    }
    for (int e = tid; e < 4096; e += 512) slog[e] = 0.f;
    __syncthreads();

    // routing: 3 iters. outputs e0=tid, e1=tid+512 of 1024 (pos*256+oc)
    int e0 = tid, e1 = tid + 512;
    float bias0 = conv_bias[e0 & 255];
    float bias1 = conv_bias[e1 & 255];
    int pos0 = e0 >> 8, oc0 = e0 & 255, o0 = oc0 >> 3;
    int pos1 = e1 >> 8, oc1 = e1 & 255, o1 = oc1 >> 3;
    float act0 = 0.f, act1 = 0.f;

    for (int it = 0; it < 3; it++) {
        // warp-parallel softmax: 128 rows (pos*32+i), 16 warps x 8 rows
#pragma unroll
        for (int rr = 0; rr < 8; rr++) {
            int row = wid + rr * 16;
            float v = slog[row * 32 + lane];
            float m = v;
#pragma unroll
            for (int d = 16; d; d >>= 1) m = fmaxf(m, __shfl_xor_sync(0xFFFFFFFFu, m, d));
            float e = expf(v - m);
            float z = e;
#pragma unroll
            for (int d = 16; d; d >>= 1) z += __shfl_xor_sync(0xFFFFFFFFu, z, d);
            srt[row * 32 + lane] = e / z;
        }
        __syncthreads();
        // preact + shfl squash for e0, e1 (lane alignment: e&7 == lane&7 groups)
        float s0 = bias0, s1 = bias1;
        for (int i = 0; i < 32; i++) {
            s0 += srt[(pos0 * 32 + i) * 32 + o0] * svf[(pos0 * 32 + i) * 256 + oc0];
            s1 += srt[(pos1 * 32 + i) * 32 + o1] * svf[(pos1 * 32 + i) * 256 + oc1];
        }
        float n0 = s0 * s0, n1 = s1 * s1;
        n0 += __shfl_xor_sync(0xFFFFFFFFu, n0, 1);
        n0 += __shfl_xor_sync(0xFFFFFFFFu, n0, 2);
        n0 += __shfl_xor_sync(0xFFFFFFFFu, n0, 4);
        n1 += __shfl_xor_sync(0xFFFFFFFFu, n1, 1);
        n1 += __shfl_xor_sync(0xFFFFFFFFu, n1, 2);
        n1 += __shfl_xor_sync(0xFFFFFFFFu, n1, 4);
        float f0 = (n0 / (1.f + n0)) * rsqrtf(n0 + 1e-8f);
        float f1 = (n1 / (1.f + n1)) * rsqrtf(n1 + 1e-8f);
        act0 = s0 * f0;
        act1 = s1 * f1;
        sact[e0] = act0;
        sact[e1] = act1;
        __syncthreads();
        if (it < 2) {
            for (int e = tid; e < 4096; e += 512) {
                int row = e >> 5;               // pos*32 + i
                int oo = e & 31;
                int pp = e >> 10;
                float d = 0.f;
#pragma unroll
                for (int aa = 0; aa < 8; aa++)
                    d += svf[row * 256 + oo * 8 + aa] * sact[pp * 256 + oo * 8 + aa];
                slog[e] += d;
            }
            __syncthreads();
        }
    }
    {
        int a0 = oc0 & 7, a1 = oc1 & 7;
        g_c[((b * 32 + o0) * 8 + a0) * 4 + pos0] = act0;
        g_c[((b * 32 + o1) * 8 + a1) * 4 + pos1] = act1;
    }
}

// ---------------- digit caps (warp-parallel softmax + shfl squash) ----------------
__global__ __launch_bounds__(256) void digit_kernel(
    const float* __restrict__ digit_w, const float* __restrict__ digit_bias,
    const float* __restrict__ y, float* __restrict__ out_dcap) {
    __shared__ float smem[11264];
    float* sc = smem;
    float* sdw = smem + 1024;
    float* sv = smem + 6144;
    int b = blockIdx.x, tid = threadIdx.x;
    int warp = tid >> 5, lane = tid & 31;
    for (int idx = tid; idx < 1024; idx += 256) sc[idx] = g_c[b * 1024 + idx];
    for (int idx = tid; idx < 5120; idx += 256) sdw[idx] = digit_w[idx];
    __syncthreads();
    for (int idx = tid; idx < 5120; idx += 256) {
        int i = idx / 160, oa = idx % 160;
        float s = 0.f;
        const float* ci = &sc[i * 32];
        const float* wv = &sdw[oa * 32];
#pragma unroll
        for (int z = 0; z < 32; z++) s += ci[z] * wv[z];
        sv[(i * 10 + (oa >> 4)) * 16 + (oa & 15)] = s;
    }
    __syncthreads();
    float* slog = smem;
    float* sroute = smem + 320;
    float* sact = smem + 640;
    for (int e = tid; e < 320; e += 256) slog[e] = 0.f;
    __syncthreads();

    float bias = (tid < 160) ? digit_bias[tid] : 0.f;
    float act = 0.f;

    for (int it = 0; it < 3; it++) {
#pragma unroll
        for (int rr = 0; rr < 4; rr++) {
            int i = warp + rr * 8;
            float v = (lane < 10) ? slog[i * 10 + lane] : -1e30f;
            float m = v;
#pragma unroll
            for (int d = 16; d; d >>= 1) m = fmaxf(m, __shfl_xor_sync(0xFFFFFFFFu, m, d));
            float e = (lane < 10) ? expf(v - m) : 0.f;
            float z = e;
#pragma unroll
            for (int d = 16; d; d >>= 1) z += __shfl_xor_sync(0xFFFFFFFFu, z, d);
            if (lane < 10) sroute[i * 10 + lane] = e / z;
        }
        __syncthreads();
        if (tid < 160) {
            int o = tid >> 4, a = tid & 15;
            float s = bias;
            for (int i = 0; i < 32; i++)
                s += sroute[i * 10 + o] * sv[(i * 10 + o) * 16 + a];
            float n2 = s * s;
            n2 += __shfl_xor_sync(0xFFFFFFFFu, n2, 1);
            n2 += __shfl_xor_sync(0xFFFFFFFFu, n2, 2);
            n2 += __shfl_xor_sync(0xFFFFFFFFu, n2, 4);
            n2 += __shfl_xor_sync(0xFFFFFFFFu, n2, 8);
            float f = (n2 / (1.f + n2)) * rsqrtf(n2 + 1e-8f);
            act = s * f;
            sact[tid] = act;
        }
        __syncthreads();
        if (it < 2) {
            for (int e = tid; e < 320; e += 256) {
                int o = e % 10;
                float d = 0.f;
#pragma unroll
                for (int a = 0; a < 16; a++) d += sv[e * 16 + a] * sact[o * 16 + a];
                slog[e] += d;
            }
            __syncthreads();
        }
    }
    if (tid < 160) {
        int o = tid >> 4;
        out_dcap[b * 160 + tid] = act;
        g_masked[b * 160 + tid] = act * y[b * 10 + o];
    }
}

// ---------------- FC via mma.sync: M=512, per block 128xM, 256xN, K tiles of 64 --------
#define F_AH 0
#define F_AL 18432
#define F_BH 36864
#define F_SMEM 73728

template <int ACT>
__global__ __launch_bounds__(512, 1) void fc_mma_kernel(
    const float* __restrict__ A, const unsigned short* __restrict__ Bw,
    const float* __restrict__ bias, float* __restrict__ C,
    int K_real, int KT, int N_pad, int N_real) {
    extern __shared__ char fsm[];
    int tid = threadIdx.x;
    int n0 = blockIdx.x * 256;
    int m0 = blockIdx.y * 128;
    int wid = tid >> 5, lane = tid & 31;
    int g = lane >> 2, c = lane & 3;
    int warpM = wid & 1;
    int warpN = wid >> 1;

    uint32_t sbase = smem_u32(fsm);
    uint32_t aBase = sbase + F_AH +
                     (uint32_t)(warpM * 64 + (lane & 15)) * PITCH + ((lane >> 4) << 4);
    uint32_t bBase = sbase + F_BH +
                     (uint32_t)(warpN * 32 + (lane & 7) + ((lane & 16) >> 1)) * PITCH +
                     ((lane & 8) ? 16u : 0u);
    uint32_t* ah = (uint32_t*)(fsm + F_AH);
    uint32_t* al = (uint32_t*)(fsm + F_AL);

    float acc[4][4][4];
#pragma unroll
    for (int mt = 0; mt < 4; mt++)
#pragma unroll
        for (int j = 0; j < 4; j++)
#pragma unroll
            for (int q = 0; q < 4; q++) acc[mt][j][q] = 0.f;

    for (int q = 0; q < KT; q++) {
        if (q > 0) __syncthreads();
        {
            size_t wbase = (size_t)q * N_pad * 64 + (size_t)n0 * 64;
#pragma unroll
            for (int ii = 0; ii < 4; ii++) {
                int idx = tid + ii * 512;
                int r = idx >> 3, seg = idx & 7;
                cp16(fsm + F_BH + r * PITCH + seg * 16, &Bw[wbase + r * 64 + seg * 8]);
            }
            cp_commit();
        }
#pragma unroll
        for (int ii = 0; ii < 8; ii++) {
            int idx = tid + ii * 512;
            int r = idx >> 5, cw = idx & 31;
            int k0 = q * 64 + cw * 2;
            const float* src = &A[(size_t)(m0 + r) * K_real + k0];
            float v0 = (k0 < K_real) ? src[0] : 0.f;
            float v1 = (k0 + 1 < K_real) ? src[1] : 0.f;
            __nv_bfloat16 h0 = __float2bfloat16(v0);
            __nv_bfloat16 h1 = __float2bfloat16(v1);
            int off = r * (PITCH >> 2) + cw;
            ah[off] = (uint32_t)__bfloat16_as_ushort(h0) |
                      ((uint32_t)__bfloat16_as_ushort(h1) << 16);
            al[off] = pack_bf16x2(v0 - __bfloat162float(h0), v1 - __bfloat162float(h1));
        }
        cp_wait0();
        __syncthreads();
#pragma unroll
        for (int kk = 0; kk < 4; kk++) {
            uint32_t bh[2][4];
#pragma unroll
            for (int np = 0; np < 2; np++)
                ldm_x4(bh[np], bBase + np * (16 * PITCH) + kk * 32);
#pragma unroll
            for (int mt = 0; mt < 4; mt++) {
                uint32_t ahf[4], alf[4];
                ldm_x4(ahf, aBase + mt * (16 * PITCH) + kk * 32);
                ldm_x4(alf, aBase + (F_AL - F_AH) + mt * (16 * PITCH) + kk * 32);
#pragma unroll
                for (int np = 0; np < 2; np++)
#pragma unroll
                    for (int nt = 0; nt < 2; nt++)
                        mma_bf16(acc[mt][np * 2 + nt], ahf, bh[np][nt * 2], bh[np][nt * 2 + 1]);
#pragma unroll
                for (int np = 0; np < 2; np++)
#pragma unroll
                    for (int nt = 0; nt < 2; nt++)
                        mma_bf16(acc[mt][np * 2 + nt], alf, bh[np][nt * 2], bh[np][nt * 2 + 1]);
            }
        }
    }

#pragma unroll
    for (int mt = 0; mt < 4; mt++) {
        int R1 = m0 + warpM * 64 + mt * 16 + g;
        int R2 = R1 + 8;
#pragma unroll
        for (int j = 0; j < 4; j++) {
            int col = n0 + warpN * 32 + j * 8 + 2 * c;
            if (col >= N_real) continue;
            float bv0 = __ldg(&bias[col]);
            float bv1 = __ldg(&bias[col + 1]);
            float v0 = acc[mt][j][0] + bv0;
            float v1 = acc[mt][j][1] + bv1;
            float v2 = acc[mt][j][2] + bv0;
            float v3 = acc[mt][j][3] + bv1;
            if (ACT == 1) {
                v0 = v0 > 0.f ? v0 : 0.f; v1 = v1 > 0.f ? v1 : 0.f;
                v2 = v2 > 0.f ? v2 : 0.f; v3 = v3 > 0.f ? v3 : 0.f;
            } else {
                v0 = 1.f / (1.f + expf(-v0)); v1 = 1.f / (1.f + expf(-v1));
                v2 = 1.f / (1.f + expf(-v2)); v3 = 1.f / (1.f + expf(-v3));
            }
            *(float2*)&C[(size_t)R1 * N_real + col] = make_float2(v0, v1);
            *(float2*)&C[(size_t)R2 * N_real + col] = make_float2(v2, v3);
        }
    }
}

// ---------------- launcher ----------------
extern "C" void kernel_launch(void* const* d_in, const int* in_sizes, int n_in,
                              void* d_out, int out_size) {
    const float* x = (const float*)d_in[0];
    const float* y = (const float*)d_in[1];
    const float* conv1_w = (const float*)d_in[2];
    const float* conv1_b = (const float*)d_in[3];
    const float* prim_w = (const float*)d_in[4];
    const float* prim_bias = (const float*)d_in[5];
    const float* conv_w = (const float*)d_in[6];
    const float* conv_bias = (const float*)d_in[7];
    const float* digit_w = (const float*)d_in[8];
    const float* digit_bias = (const float*)d_in[9];
    const float* fc1_w = (const float*)d_in[10];
    const float* fc1_b = (const float*)d_in[11];
    const float* fc2_w = (const float*)d_in[12];
    const float* fc2_b = (const float*)d_in[13];
    const float* fc3_w = (const float*)d_in[14];
    const float* fc3_b = (const float*)d_in[15];
    float* out = (float*)d_out;              // [0:81920) dcap, [81920:483328) recon

    static float *p_masked = nullptr, *p_r1 = nullptr, *p_r2 = nullptr;
    static unsigned short *p_fw1 = nullptr, *p_fw2 = nullptr, *p_fw3 = nullptr;
    static bool attrs_set = false;
    if (!p_masked) {
        cudaGetSymbolAddress((void**)&p_masked, g_masked);
        cudaGetSymbolAddress((void**)&p_r1, g_r1);
        cudaGetSymbolAddress((void**)&p_r2, g_r2);
        cudaGetSymbolAddress((void**)&p_fw1, g_fw1);
        cudaGetSymbolAddress((void**)&p_fw2, g_fw2);
        cudaGetSymbolAddress((void**)&p_fw3, g_fw3);
    }
    if (!attrs_set) {
        cudaFuncSetAttribute(prim_mma_kernel, cudaFuncAttributeMaxDynamicSharedMemorySize,
                             PRIM_SMEM);
        cudaFuncSetAttribute(conv1_mma_kernel, cudaFuncAttributeMaxDynamicSharedMemorySize,
                             C1_SMEM);
        cudaFuncSetAttribute(cc_votes_rout_kernel, cudaFuncAttributeMaxDynamicSharedMemorySize,
                             V_SMEM);
        cudaFuncSetAttribute(fc_mma_kernel<1>, cudaFuncAttributeMaxDynamicSharedMemorySize,
                             F_SMEM);
        cudaFuncSetAttribute(fc_mma_kernel<2>, cudaFuncAttributeMaxDynamicSharedMemorySize,
                             F_SMEM);
        attrs_set = true;
    }

    // weight prep
    prepack_W<<<(25 * 4 * 256 * 64 + 255) / 256, 256>>>(prim_w);
    prepack_c1<<<(256 * 96 + 255) / 256, 256>>>(conv1_w);
    prepack_cc<<<(4 * 256 * 64 + 255) / 256, 256>>>(conv_w);
    prepack_fc<<<(3 * 512 * 64 + 255) / 256, 256>>>(fc1_w, p_fw1, 160, 512, 512,
                                                    3 * 512 * 64);
    prepack_fc<<<(8 * 1024 * 64 + 255) / 256, 256>>>(fc2_w, p_fw2, 512, 1024, 1024,
                                                     8 * 1024 * 64);
    prepack_fc<<<(16 * 1024 * 64 + 255) / 256, 256>>>(fc3_w, p_fw3, 1024, 784, 1024,
                                                      16 * 1024 * 64);

    // conv1 + relu via tensor cores
    conv1_mma_kernel<<<1600, 512, C1_SMEM>>>(x, conv1_b);

    // primary caps conv via mma.sync + fused squash
    prim_mma_kernel<<<256, 512, PRIM_SMEM>>>(prim_bias);

    // fused conv-caps votes (mma.sync) + routing
    cc_votes_rout_kernel<<<512, 512, V_SMEM>>>(conv_bias);

    // digit caps (warp-parallel softmax)
    digit_kernel<<<512, 256>>>(digit_w, digit_bias, y, out);

    // FC reconstruction chain via mma.sync
    fc_mma_kernel<1><<<dim3(2, 4), 512, F_SMEM>>>(p_masked, p_fw1, fc1_b, p_r1,
                                                  160, 3, 512, 512);
    fc_mma_kernel<1><<<dim3(4, 4), 512, F_SMEM>>>(p_r1, p_fw2, fc2_b, p_r2,
                                                  512, 8, 1024, 1024);
    fc_mma_kernel<2><<<dim3(4, 4), 512, F_SMEM>>>(p_r2, p_fw3, fc3_b, out + 81920,
                                                  1024, 16, 1024, 784);
}